// round 3
// baseline (speedup 1.0000x reference)
#include <cuda_runtime.h>

// Problem constants (fixed by the dataset)
#define B_  4
#define S_  2048
#define E_  512
#define Q_  8
#define F_  2048           // FFN
#define M_  (B_ * S_)      // 8192 tokens

// Tiling
#define BM 128
#define BN 128
#define BK 32
#define NTHREADS 256

// out[m, e] = sum_k relu( b1[k] + sum_q cos(theta[q])*cos(x[m, q]) * W1[q, k] ) * W2[k, e] + b2[e]
__global__ __launch_bounds__(NTHREADS, 2)
void ffq_fused_kernel(const float* __restrict__ x,
                      const float* __restrict__ theta,
                      const float* __restrict__ W1,
                      const float* __restrict__ b1,
                      const float* __restrict__ W2,
                      const float* __restrict__ b2,
                      float* __restrict__ out) {
    __shared__ float zs[Q_][BM];        // z tile, transposed: zs[q][m]
    __shared__ float w1s[Q_][BK];       // W1 chunk
    __shared__ float b1s[BK];           // b1 chunk
    __shared__ float hs[BK][BM];        // h chunk (k-major rows of m)
    __shared__ float w2s[BK][BN];       // W2 chunk (k-major rows of n)

    const int tid = threadIdx.x;
    const int m0  = blockIdx.x * BM;
    const int n0  = blockIdx.y * BN;

    const int ty = tid >> 4;            // 0..15 -> output rows  ty*8 .. ty*8+7
    const int tx = tid & 15;            // 0..15 -> output cols  tx*8 .. tx*8+7

    // W2 staging addresses for this thread: 4 float4 per chunk
    const int w2k  = tid >> 5;          // base row 0..7 (row stride 8 per r)
    const int w2n4 = tid & 31;          // float4 column

    // ---- z tile: zs[q][m] = cos(theta[q]) * cos(x[(m0+m)*E + q]) ----
    #pragma unroll
    for (int r = 0; r < (Q_ * BM) / NTHREADS; r++) {
        int idx = tid + r * NTHREADS;
        int q = idx >> 7;               // / BM
        int m = idx & (BM - 1);
        float xv = x[(size_t)(m0 + m) * E_ + q];
        zs[q][m] = cosf(theta[q]) * cosf(xv);
    }

    // ---- prefetch W2 chunk 0 into registers ----
    float4 w2r[4];
    #pragma unroll
    for (int r = 0; r < 4; r++)
        w2r[r] = *reinterpret_cast<const float4*>(
            &W2[(size_t)(w2k + r * 8) * E_ + n0 + w2n4 * 4]);

    float acc[8][8];
    #pragma unroll
    for (int i = 0; i < 8; i++)
        #pragma unroll
        for (int j = 0; j < 8; j++) acc[i][j] = 0.0f;

    for (int k0 = 0; k0 < F_; k0 += BK) {
        __syncthreads();   // previous iteration's FMA reads of hs/w2s are done

        // ---- commit prefetched W2 chunk to smem ----
        #pragma unroll
        for (int r = 0; r < 4; r++)
            *reinterpret_cast<float4*>(&w2s[w2k + r * 8][w2n4 * 4]) = w2r[r];

        // ---- stage W1 chunk (8x32) and b1 chunk (32) ----
        // NOTE: separate ifs — Q_*BK == NTHREADS, so an else-branch would be dead.
        {
            int q = tid >> 5;           // 0..7
            int k = tid & (BK - 1);
            w1s[q][k] = W1[q * F_ + k0 + k];
        }
        if (tid < BK) {
            b1s[tid] = b1[k0 + tid];
        }

        // ---- issue prefetch of NEXT W2 chunk (latency hidden under compute) ----
        if (k0 + BK < F_) {
            #pragma unroll
            for (int r = 0; r < 4; r++)
                w2r[r] = *reinterpret_cast<const float4*>(
                    &W2[(size_t)(k0 + BK + w2k + r * 8) * E_ + n0 + w2n4 * 4]);
        }
        __syncthreads();   // w1s/b1s/w2s visible

        // ---- compute h chunk: hs[k][m] = relu(b1 + z(m,:) . W1(:,k)) ----
        #pragma unroll
        for (int r = 0; r < (BK * BM) / NTHREADS; r++) {
            int idx = tid + r * NTHREADS;
            int k = idx >> 7;                   // / BM
            int m = idx & (BM - 1);
            float a = b1s[k];
            #pragma unroll
            for (int q = 0; q < Q_; q++) a = fmaf(zs[q][m], w1s[q][k], a);
            hs[k][m] = fmaxf(a, 0.0f);
        }
        __syncthreads();   // hs visible

        // ---- 128x128x32 register-tiled FMA ----
        #pragma unroll
        for (int k = 0; k < BK; k++) {
            float af[8], bf[8];
            *reinterpret_cast<float4*>(&af[0]) = *reinterpret_cast<float4*>(&hs[k][ty * 8]);
            *reinterpret_cast<float4*>(&af[4]) = *reinterpret_cast<float4*>(&hs[k][ty * 8 + 4]);
            *reinterpret_cast<float4*>(&bf[0]) = *reinterpret_cast<float4*>(&w2s[k][tx * 8]);
            *reinterpret_cast<float4*>(&bf[4]) = *reinterpret_cast<float4*>(&w2s[k][tx * 8 + 4]);
            #pragma unroll
            for (int i = 0; i < 8; i++)
                #pragma unroll
                for (int j = 0; j < 8; j++)
                    acc[i][j] = fmaf(af[i], bf[j], acc[i][j]);
        }
    }

    // ---- epilogue: add b2, store float4 ----
    float bb[8];
    #pragma unroll
    for (int j = 0; j < 8; j++) bb[j] = b2[n0 + tx * 8 + j];

    #pragma unroll
    for (int i = 0; i < 8; i++) {
        size_t row = (size_t)(m0 + ty * 8 + i);
        float4 v0, v1;
        v0.x = acc[i][0] + bb[0]; v0.y = acc[i][1] + bb[1];
        v0.z = acc[i][2] + bb[2]; v0.w = acc[i][3] + bb[3];
        v1.x = acc[i][4] + bb[4]; v1.y = acc[i][5] + bb[5];
        v1.z = acc[i][6] + bb[6]; v1.w = acc[i][7] + bb[7];
        *reinterpret_cast<float4*>(&out[row * E_ + n0 + tx * 8])     = v0;
        *reinterpret_cast<float4*>(&out[row * E_ + n0 + tx * 8 + 4]) = v1;
    }
}

extern "C" void kernel_launch(void* const* d_in, const int* in_sizes, int n_in,
                              void* d_out, int out_size) {
    // Identify inputs by element count — robust to metadata ordering.
    // All six sizes are distinct for this problem:
    //   x  = 4*2048*512 = 4194304
    //   W2 = 2048*512   = 1048576
    //   W1 = 8*2048     = 16384
    //   b1 = 2048
    //   b2 = 512
    //   theta = 8
    const float *x = nullptr, *theta = nullptr, *W1 = nullptr,
                *b1 = nullptr, *W2 = nullptr, *b2 = nullptr;
    for (int i = 0; i < n_in; i++) {
        switch (in_sizes[i]) {
            case B_ * S_ * E_: x     = (const float*)d_in[i]; break;  // 4194304
            case F_ * E_:      W2    = (const float*)d_in[i]; break;  // 1048576
            case Q_ * F_:      W1    = (const float*)d_in[i]; break;  // 16384
            case F_:           b1    = (const float*)d_in[i]; break;  // 2048
            case E_:           b2    = (const float*)d_in[i]; break;  // 512
            case Q_:           theta = (const float*)d_in[i]; break;  // 8
            default: break;
        }
    }
    float* out = (float*)d_out;

    dim3 grid(M_ / BM, E_ / BN);   // 64 x 4 = 256 CTAs
    ffq_fused_kernel<<<grid, NTHREADS>>>(x, theta, W1, b1, W2, b2, out);
}

// round 6
// speedup vs baseline: 2.9126x; 2.9126x over previous
#include <cuda_runtime.h>
#include <cstdint>

// Problem constants
#define B_  4
#define S_  2048
#define E_  512
#define Q_  8
#define F_  2048
#define M_  (B_ * S_)

// Tiling
#define BM 64
#define BN 256
#define BK 32
#define NTH 256
#define NCHUNK (F_ / BK)      // 64
#define PADA 36               // hs row stride (floats): 36 mod 32 = 4 -> conflict-free A frags
#define PADB 264              // w2s row stride (floats): 264 mod 32 = 8 -> conflict-free B frags

// SMEM layout (floats)
#define HS_F    (BM * PADA)           // 2304 floats = 9216 B
#define W2BUF_F (BK * PADB)           // 8448 floats = 33792 B
#define SMEM_TOTAL_BYTES ((HS_F + 2 * W2BUF_F) * 4)   // 76800 B

// ---------------- helpers ----------------
__device__ __forceinline__ uint32_t smem_u32(const void* p) {
    uint32_t a;
    asm("{ .reg .u64 t; cvta.to.shared.u64 t, %1; cvt.u32.u64 %0, t; }" : "=r"(a) : "l"(p));
    return a;
}
__device__ __forceinline__ float to_tf32(float f) {
    uint32_t r;
    asm("cvt.rna.tf32.f32 %0, %1;" : "=r"(r) : "f"(f));
    return __uint_as_float(r);
}
__device__ __forceinline__ uint32_t tf32_bits(float f) {
    uint32_t r;
    asm("cvt.rna.tf32.f32 %0, %1;" : "=r"(r) : "f"(f));
    return r;
}
__device__ __forceinline__ void cp16(uint32_t dst, const void* src) {
    asm volatile("cp.async.cg.shared.global [%0], [%1], 16;" :: "r"(dst), "l"(src));
}
#define CP_COMMIT() asm volatile("cp.async.commit_group;" ::: "memory")
#define CP_WAIT1()  asm volatile("cp.async.wait_group 1;" ::: "memory")
#define CP_WAIT0()  asm volatile("cp.async.wait_group 0;" ::: "memory")

// D(16x8,f32) += A(16x8,tf32 row) * B(8x8,tf32 col)
__device__ __forceinline__ void mma8(float* d, const uint32_t* a, const uint32_t* b) {
    asm volatile(
        "mma.sync.aligned.m16n8k8.row.col.f32.tf32.tf32.f32 "
        "{%0,%1,%2,%3}, {%4,%5,%6,%7}, {%8,%9}, {%0,%1,%2,%3};"
        : "+f"(d[0]), "+f"(d[1]), "+f"(d[2]), "+f"(d[3])
        : "r"(a[0]), "r"(a[1]), "r"(a[2]), "r"(a[3]), "r"(b[0]), "r"(b[1]));
}

// ---------------- fused kernel ----------------
// out[m,e] = sum_k relu(b1[k] + sum_q cos(th[q])cos(x[m,q]) W1[q,k]) * W2[k,e] + b2[e]
__global__ __launch_bounds__(NTH, 2)
void ffq_mma_kernel(const float* __restrict__ x,
                    const float* __restrict__ theta,
                    const float* __restrict__ W1,
                    const float* __restrict__ b1,
                    const float* __restrict__ W2,
                    const float* __restrict__ b2,
                    float* __restrict__ out) {
    extern __shared__ float smf[];
    float* hs = smf;                       // [BM][PADA]
    float* w2s = smf + HS_F;               // [2][BK][PADB]
    const uint32_t sb_w2 = smem_u32(w2s);

    const int tid = threadIdx.x;
    const int w   = tid >> 5;
    const int l   = tid & 31;
    const int m0  = blockIdx.x * BM;
    const int n0  = blockIdx.y * BN;

    // warp tile: 2 (m) x 4 (n) warps; WM=32, WN=64
    const int wm = (w & 1) * 32;
    const int wn = (w >> 1) * 64;

    // h roles: each thread owns one m-row and a k-quarter (8 k's) of the chunk
    const int hm = tid & 63;
    const int kq = tid >> 6;               // 0..3

    // ---- z registers: z[q] = cos(theta[q]) * cos(x[m0+hm, q]) ----
    float zreg[Q_];
    {
        const float4 x0 = *(const float4*)(x + (size_t)(m0 + hm) * E_);
        const float4 x1 = *(const float4*)(x + (size_t)(m0 + hm) * E_ + 4);
        zreg[0] = cosf(theta[0]) * cosf(x0.x);
        zreg[1] = cosf(theta[1]) * cosf(x0.y);
        zreg[2] = cosf(theta[2]) * cosf(x0.z);
        zreg[3] = cosf(theta[3]) * cosf(x0.w);
        zreg[4] = cosf(theta[4]) * cosf(x1.x);
        zreg[5] = cosf(theta[5]) * cosf(x1.y);
        zreg[6] = cosf(theta[6]) * cosf(x1.z);
        zreg[7] = cosf(theta[7]) * cosf(x1.w);
    }

    // ---- prologue: cp.async W2 chunk 0 into buf 0 ----
    {
        #pragma unroll
        for (int r = 0; r < 8; r++) {
            const int k = kq + 4 * r;
            cp16(sb_w2 + (uint32_t)(k * PADB + hm * 4) * 4u,
                 W2 + (size_t)k * E_ + n0 + hm * 4);
        }
        CP_COMMIT();
    }

    float acc[2][8][4];
    #pragma unroll
    for (int mt = 0; mt < 2; mt++)
        #pragma unroll
        for (int nt = 0; nt < 8; nt++)
            #pragma unroll
            for (int v = 0; v < 4; v++) acc[mt][nt][v] = 0.0f;

    for (int c = 0; c < NCHUNK; c++) {
        const int kc = c * BK;
        const int rb = c & 1;              // read buffer for this chunk

        __syncthreads();                   // prev chunk's fragment reads done -> hs writable

        // ---- issue cp.async for chunk c+1 into the other buffer ----
        if (c + 1 < NCHUNK) {
            const uint32_t dstb = sb_w2 + (uint32_t)(rb ^ 1) * (W2BUF_F * 4u);
            #pragma unroll
            for (int r = 0; r < 8; r++) {
                const int k = kq + 4 * r;
                cp16(dstb + (uint32_t)(k * PADB + hm * 4) * 4u,
                     W2 + (size_t)(kc + BK + k) * E_ + n0 + hm * 4);
            }
            CP_COMMIT();
        }

        // ---- h chunk: this thread computes 8 values (row hm, k = kq*8 .. kq*8+7) ----
        // W1/b1 via LDG: identical addresses across the m-lanes -> L1 broadcast.
        #pragma unroll
        for (int c2 = 0; c2 < 2; c2++) {
            const int kk = kq * 8 + c2 * 4;
            const float4 b1v = *(const float4*)(b1 + kc + kk);
            float h0 = b1v.x, h1 = b1v.y, h2 = b1v.z, h3 = b1v.w;
            #pragma unroll
            for (int q = 0; q < Q_; q++) {
                const float4 wv = *(const float4*)(W1 + (size_t)q * F_ + kc + kk);
                h0 = fmaf(zreg[q], wv.x, h0);
                h1 = fmaf(zreg[q], wv.y, h1);
                h2 = fmaf(zreg[q], wv.z, h2);
                h3 = fmaf(zreg[q], wv.w, h3);
            }
            float4 o;
            o.x = to_tf32(fmaxf(h0, 0.0f));
            o.y = to_tf32(fmaxf(h1, 0.0f));
            o.z = to_tf32(fmaxf(h2, 0.0f));
            o.w = to_tf32(fmaxf(h3, 0.0f));
            *(float4*)(hs + hm * PADA + kk) = o;
        }

        if (c + 1 < NCHUNK) { CP_WAIT1(); } else { CP_WAIT0(); }
        __syncthreads();                   // hs + w2s[rb] visible to all threads

        // ---- fragments + 32 mma per k-step x 4 k-steps ----
        const float* w2b = w2s + rb * W2BUF_F;
        const int g = l >> 2;              // group id 0..7
        const int t = l & 3;               // thread-in-group 0..3
        #pragma unroll
        for (int ks = 0; ks < 4; ks++) {
            const int kb = ks * 8;
            // A fragments (from tf32-rounded hs)
            uint32_t a[2][4];
            #pragma unroll
            for (int mt = 0; mt < 2; mt++) {
                const int r0 = wm + mt * 16 + g;
                const float* base = hs + r0 * PADA + kb + t;
                a[mt][0] = __float_as_uint(base[0]);
                a[mt][1] = __float_as_uint(base[8 * PADA]);
                a[mt][2] = __float_as_uint(base[4]);
                a[mt][3] = __float_as_uint(base[8 * PADA + 4]);
            }
            // B fragments (raw f32 in smem -> tf32 round at load)
            uint32_t bf[8][2];
            const int kb2 = kb + t;
            #pragma unroll
            for (int nt = 0; nt < 8; nt++) {
                const int nc = wn + nt * 8 + g;
                bf[nt][0] = tf32_bits(w2b[kb2 * PADB + nc]);
                bf[nt][1] = tf32_bits(w2b[(kb2 + 4) * PADB + nc]);
            }
            #pragma unroll
            for (int mt = 0; mt < 2; mt++)
                #pragma unroll
                for (int nt = 0; nt < 8; nt++)
                    mma8(acc[mt][nt], a[mt], bf[nt]);
        }
    }

    // ---- epilogue: add b2, store (c0,c1) and (c2,c3) as float2 ----
    {
        const int g = l >> 2;
        const int t = l & 3;
        #pragma unroll
        for (int nt = 0; nt < 8; nt++) {
            const int col = n0 + wn + nt * 8 + t * 2;
            const float2 bb = *(const float2*)(b2 + col);
            #pragma unroll
            for (int mt = 0; mt < 2; mt++) {
                const int r0 = m0 + wm + mt * 16 + g;
                float2 v0, v1;
                v0.x = acc[mt][nt][0] + bb.x;
                v0.y = acc[mt][nt][1] + bb.y;
                v1.x = acc[mt][nt][2] + bb.x;
                v1.y = acc[mt][nt][3] + bb.y;
                *(float2*)(out + (size_t)r0 * E_ + col)       = v0;
                *(float2*)(out + (size_t)(r0 + 8) * E_ + col) = v1;
            }
        }
    }
}

extern "C" void kernel_launch(void* const* d_in, const int* in_sizes, int n_in,
                              void* d_out, int out_size) {
    // Identify inputs by element count (order-proof; all sizes distinct)
    const float *x = nullptr, *theta = nullptr, *W1 = nullptr,
                *b1 = nullptr, *W2 = nullptr, *b2 = nullptr;
    for (int i = 0; i < n_in; i++) {
        switch (in_sizes[i]) {
            case B_ * S_ * E_: x     = (const float*)d_in[i]; break;
            case F_ * E_:      W2    = (const float*)d_in[i]; break;
            case Q_ * F_:      W1    = (const float*)d_in[i]; break;
            case F_:           b1    = (const float*)d_in[i]; break;
            case E_:           b2    = (const float*)d_in[i]; break;
            case Q_:           theta = (const float*)d_in[i]; break;
            default: break;
        }
    }
    float* out = (float*)d_out;

    // Unconditional (idempotent, capture-legal) — no static state in kernel_launch.
    cudaFuncSetAttribute(ffq_mma_kernel,
                         cudaFuncAttributeMaxDynamicSharedMemorySize,
                         SMEM_TOTAL_BYTES);

    dim3 grid(M_ / BM, E_ / BN);   // 128 x 2 = 256 CTAs, one wave at 2 CTA/SM
    ffq_mma_kernel<<<grid, NTH, SMEM_TOTAL_BYTES>>>(x, theta, W1, b1, W2, b2, out);
}

// round 7
// speedup vs baseline: 3.0886x; 1.0604x over previous
#include <cuda_runtime.h>
#include <cstdint>

// Problem constants
#define B_  4
#define S_  2048
#define E_  512
#define Q_  8
#define F_  2048
#define M_  (B_ * S_)

// Tiling
#define BM 64
#define BN 256
#define BK 32
#define NTH 256
#define NCHUNK (F_ / BK)      // 64
#define PADA 36               // hs row stride (floats): 36 mod 32 = 4 -> conflict-free A frags
#define PADB 264              // w2s row stride (floats): 264 mod 32 = 8 -> conflict-free B frags

// SMEM layout (floats): hs double-buffered now
#define HS_F    (BM * PADA)           // 2304 floats
#define W2BUF_F (BK * PADB)           // 8448 floats
#define SMEM_TOTAL_BYTES ((2 * HS_F + 2 * W2BUF_F) * 4)   // 86016 B

// W2 pre-rounded to tf32 (same [k][n] layout)
__device__ float g_W2R[(size_t)F_ * E_];

// ---------------- helpers ----------------
__device__ __forceinline__ uint32_t smem_u32(const void* p) {
    uint32_t a;
    asm("{ .reg .u64 t; cvta.to.shared.u64 t, %1; cvt.u32.u64 %0, t; }" : "=r"(a) : "l"(p));
    return a;
}
__device__ __forceinline__ float to_tf32(float f) {
    uint32_t r;
    asm("cvt.rna.tf32.f32 %0, %1;" : "=r"(r) : "f"(f));
    return __uint_as_float(r);
}
__device__ __forceinline__ void cp16(uint32_t dst, const void* src) {
    asm volatile("cp.async.cg.shared.global [%0], [%1], 16;" :: "r"(dst), "l"(src));
}
#define CP_COMMIT() asm volatile("cp.async.commit_group;" ::: "memory")
#define CP_WAIT0()  asm volatile("cp.async.wait_group 0;" ::: "memory")

// D(16x8,f32) += A(16x8,tf32 row) * B(8x8,tf32 col)
__device__ __forceinline__ void mma8(float* d, const uint32_t* a, const uint32_t* b) {
    asm volatile(
        "mma.sync.aligned.m16n8k8.row.col.f32.tf32.tf32.f32 "
        "{%0,%1,%2,%3}, {%4,%5,%6,%7}, {%8,%9}, {%0,%1,%2,%3};"
        : "+f"(d[0]), "+f"(d[1]), "+f"(d[2]), "+f"(d[3])
        : "r"(a[0]), "r"(a[1]), "r"(a[2]), "r"(a[3]), "r"(b[0]), "r"(b[1]));
}

// ---------------- prepass: g_W2R = tf32_round(W2) ----------------
__global__ void w2_round_kernel(const float* __restrict__ W2) {
    const int idx = (blockIdx.x * 256 + threadIdx.x);
    float4 v = ((const float4*)W2)[idx];
    float4 o;
    o.x = to_tf32(v.x); o.y = to_tf32(v.y);
    o.z = to_tf32(v.z); o.w = to_tf32(v.w);
    ((float4*)g_W2R)[idx] = o;
}

// ---------------- fused kernel ----------------
// out[m,e] = sum_k relu(b1[k] + sum_q cos(th[q])cos(x[m,q]) W1[q,k]) * W2[k,e] + b2[e]
__global__ __launch_bounds__(NTH, 2)
void ffq_mma_kernel(const float* __restrict__ x,
                    const float* __restrict__ theta,
                    const float* __restrict__ W1,
                    const float* __restrict__ b1,
                    const float* __restrict__ b2,
                    float* __restrict__ out) {
    extern __shared__ float smf[];
    float* hsbuf = smf;                    // [2][BM][PADA]
    float* w2s   = smf + 2 * HS_F;         // [2][BK][PADB]
    const uint32_t sb_w2 = smem_u32(w2s);

    const int tid = threadIdx.x;
    const int w   = tid >> 5;
    const int l   = tid & 31;
    const int m0  = blockIdx.x * BM;
    const int n0  = blockIdx.y * BN;

    // warp tile: 2 (m) x 4 (n) warps; WM=32, WN=64
    const int wm = (w & 1) * 32;
    const int wn = (w >> 1) * 64;

    // h roles: each thread owns one m-row and a k-quarter (8 k's) of the chunk
    const int hm = tid & 63;
    const int kq = tid >> 6;               // 0..3

    // ---- z registers ----
    float zreg[Q_];
    {
        const float4 x0 = *(const float4*)(x + (size_t)(m0 + hm) * E_);
        const float4 x1 = *(const float4*)(x + (size_t)(m0 + hm) * E_ + 4);
        zreg[0] = cosf(theta[0]) * cosf(x0.x);
        zreg[1] = cosf(theta[1]) * cosf(x0.y);
        zreg[2] = cosf(theta[2]) * cosf(x0.z);
        zreg[3] = cosf(theta[3]) * cosf(x0.w);
        zreg[4] = cosf(theta[4]) * cosf(x1.x);
        zreg[5] = cosf(theta[5]) * cosf(x1.y);
        zreg[6] = cosf(theta[6]) * cosf(x1.z);
        zreg[7] = cosf(theta[7]) * cosf(x1.w);
    }

    // ---- prologue: cp.async chunk 0 -> buf0; compute h(0) -> hs[0] ----
    {
        #pragma unroll
        for (int r = 0; r < 8; r++) {
            const int k = kq + 4 * r;
            cp16(sb_w2 + (uint32_t)(k * PADB + hm * 4) * 4u,
                 g_W2R + (size_t)k * E_ + n0 + hm * 4);
        }
        CP_COMMIT();
    }
    {
        float* hs0 = hsbuf;                // buffer 0
        #pragma unroll
        for (int c2 = 0; c2 < 2; c2++) {
            const int kk = kq * 8 + c2 * 4;
            const float4 b1v = *(const float4*)(b1 + kk);
            float h0 = b1v.x, h1 = b1v.y, h2 = b1v.z, h3 = b1v.w;
            #pragma unroll
            for (int q = 0; q < Q_; q++) {
                const float4 wv = *(const float4*)(W1 + (size_t)q * F_ + kk);
                h0 = fmaf(zreg[q], wv.x, h0);
                h1 = fmaf(zreg[q], wv.y, h1);
                h2 = fmaf(zreg[q], wv.z, h2);
                h3 = fmaf(zreg[q], wv.w, h3);
            }
            float4 o;
            o.x = to_tf32(fmaxf(h0, 0.0f));
            o.y = to_tf32(fmaxf(h1, 0.0f));
            o.z = to_tf32(fmaxf(h2, 0.0f));
            o.w = to_tf32(fmaxf(h3, 0.0f));
            *(float4*)(hs0 + hm * PADA + kk) = o;
        }
    }

    float acc[2][8][4];
    #pragma unroll
    for (int mt = 0; mt < 2; mt++)
        #pragma unroll
        for (int nt = 0; nt < 8; nt++)
            #pragma unroll
            for (int v = 0; v < 4; v++) acc[mt][nt][v] = 0.0f;

    const int g = l >> 2;                  // 0..7
    const int t = l & 3;                   // 0..3

    for (int c = 0; c < NCHUNK; c++) {
        const int rb = c & 1;

        CP_WAIT0();          // cp(c) complete (issued one full iteration ago)
        __syncthreads();     // cp(c) + h(c) writes visible; prior reads of other buffers done

        // ---- issue cp.async for chunk c+1 into the other w2 buffer ----
        if (c + 1 < NCHUNK) {
            const uint32_t dstb = sb_w2 + (uint32_t)(rb ^ 1) * (W2BUF_F * 4u);
            const float* src = g_W2R + (size_t)(c + 1) * BK * E_ + n0;
            #pragma unroll
            for (int r = 0; r < 8; r++) {
                const int k = kq + 4 * r;
                cp16(dstb + (uint32_t)(k * PADB + hm * 4) * 4u,
                     src + (size_t)k * E_ + hm * 4);
            }
            CP_COMMIT();
        }

        // ---- compute h(c+1) into hs[(c+1)&1] — independent of MMA(c) below;
        //      ptxas interleaves these FFMAs with the HMMA stream ----
        if (c + 1 < NCHUNK) {
            const int kc1 = (c + 1) * BK;
            float* hsn = hsbuf + (rb ^ 1) * HS_F;
            #pragma unroll
            for (int c2 = 0; c2 < 2; c2++) {
                const int kk = kq * 8 + c2 * 4;
                const float4 b1v = *(const float4*)(b1 + kc1 + kk);
                float h0 = b1v.x, h1 = b1v.y, h2 = b1v.z, h3 = b1v.w;
                #pragma unroll
                for (int q = 0; q < Q_; q++) {
                    const float4 wv = *(const float4*)(W1 + (size_t)q * F_ + kc1 + kk);
                    h0 = fmaf(zreg[q], wv.x, h0);
                    h1 = fmaf(zreg[q], wv.y, h1);
                    h2 = fmaf(zreg[q], wv.z, h2);
                    h3 = fmaf(zreg[q], wv.w, h3);
                }
                float4 o;
                o.x = to_tf32(fmaxf(h0, 0.0f));
                o.y = to_tf32(fmaxf(h1, 0.0f));
                o.z = to_tf32(fmaxf(h2, 0.0f));
                o.w = to_tf32(fmaxf(h3, 0.0f));
                *(float4*)(hsn + hm * PADA + kk) = o;
            }
        }

        // ---- MMA(c): fragments from hs[rb] / w2s[rb] (both pre-rounded tf32) ----
        const float* hsc = hsbuf + rb * HS_F;
        const float* w2b = w2s + rb * W2BUF_F;
        #pragma unroll
        for (int ks = 0; ks < 4; ks++) {
            const int kb = ks * 8;
            uint32_t a[2][4];
            #pragma unroll
            for (int mt = 0; mt < 2; mt++) {
                const int r0 = wm + mt * 16 + g;
                const float* base = hsc + r0 * PADA + kb + t;
                a[mt][0] = __float_as_uint(base[0]);
                a[mt][1] = __float_as_uint(base[8 * PADA]);
                a[mt][2] = __float_as_uint(base[4]);
                a[mt][3] = __float_as_uint(base[8 * PADA + 4]);
            }
            uint32_t bf[8][2];
            const int kb2 = kb + t;
            #pragma unroll
            for (int nt = 0; nt < 8; nt++) {
                const int nc = wn + nt * 8 + g;
                bf[nt][0] = __float_as_uint(w2b[kb2 * PADB + nc]);
                bf[nt][1] = __float_as_uint(w2b[(kb2 + 4) * PADB + nc]);
            }
            #pragma unroll
            for (int mt = 0; mt < 2; mt++)
                #pragma unroll
                for (int nt = 0; nt < 8; nt++)
                    mma8(acc[mt][nt], a[mt], bf[nt]);
        }
    }

    // ---- epilogue: add b2, store ----
    {
        #pragma unroll
        for (int nt = 0; nt < 8; nt++) {
            const int col = n0 + wn + nt * 8 + t * 2;
            const float2 bb = *(const float2*)(b2 + col);
            #pragma unroll
            for (int mt = 0; mt < 2; mt++) {
                const int r0 = m0 + wm + mt * 16 + g;
                float2 v0, v1;
                v0.x = acc[mt][nt][0] + bb.x;
                v0.y = acc[mt][nt][1] + bb.y;
                v1.x = acc[mt][nt][2] + bb.x;
                v1.y = acc[mt][nt][3] + bb.y;
                *(float2*)(out + (size_t)r0 * E_ + col)       = v0;
                *(float2*)(out + (size_t)(r0 + 8) * E_ + col) = v1;
            }
        }
    }
}

extern "C" void kernel_launch(void* const* d_in, const int* in_sizes, int n_in,
                              void* d_out, int out_size) {
    // Identify inputs by element count (order-proof; all sizes distinct)
    const float *x = nullptr, *theta = nullptr, *W1 = nullptr,
                *b1 = nullptr, *W2 = nullptr, *b2 = nullptr;
    for (int i = 0; i < n_in; i++) {
        switch (in_sizes[i]) {
            case B_ * S_ * E_: x     = (const float*)d_in[i]; break;
            case F_ * E_:      W2    = (const float*)d_in[i]; break;
            case Q_ * F_:      W1    = (const float*)d_in[i]; break;
            case F_:           b1    = (const float*)d_in[i]; break;
            case E_:           b2    = (const float*)d_in[i]; break;
            case Q_:           theta = (const float*)d_in[i]; break;
            default: break;
        }
    }
    float* out = (float*)d_out;

    cudaFuncSetAttribute(ffq_mma_kernel,
                         cudaFuncAttributeMaxDynamicSharedMemorySize,
                         SMEM_TOTAL_BYTES);

    // prepass: tf32-round W2 (1048576 elems = 262144 float4)
    w2_round_kernel<<<(F_ * E_ / 4) / 256, 256>>>(W2);

    dim3 grid(M_ / BM, E_ / BN);   // 128 x 2 = 256 CTAs
    ffq_mma_kernel<<<grid, NTH, SMEM_TOTAL_BYTES>>>(x, theta, W1, b1, b2, out);
}